// round 14
// baseline (speedup 1.0000x reference)
#include <cuda_runtime.h>
#include <math.h>
#include <stdint.h>

#define NN 50000
#define EE 800000
#define INF_F 128
#define OUTF 64
#define HH 4
#define DD 16

#define CSR_BLOCKS 782            // ceil(800000/1024) edge slices
#define QKV_BLOCKS 1563           // ceil(50000/32)
#define QKV_SMEM  (98304 + 16384) // 96KB W + 16KB x tile -> 2 blocks/SM

// ---------------- device scratch (no allocations allowed) ----------------
// Invariants maintained ACROSS calls (restored within each call):
//   g_cnt[] == 0  (zero-init at load; alloc_kernel re-zeroes after reading)
//   g_total == 0  (zero-init at load; scatter_kernel resets)
__device__ float g_q[NN * OUTF];
__device__ float g_k[NN * OUTF];
__device__ float g_v[NN * OUTF];
__device__ float g_att[NN * OUTF];
__device__ float g_qq[NN * HH];
__device__ float g_kk[NN * HH];
__device__ int   g_cnt[NN];
__device__ int   g_rs[NN];
__device__ int   g_cur[NN];
__device__ int   g_csr[EE];
__device__ int   g_is64;
__device__ int   g_total;

// packed f32x2 FMA: d = a*b + c elementwise on packed pairs (Blackwell FFMA2)
__device__ __forceinline__ unsigned long long ffma2(
    unsigned long long a, unsigned long long b, unsigned long long c)
{
    unsigned long long d;
    asm("fma.rn.f32x2 %0, %1, %2, %3;" : "=l"(d) : "l"(a), "l"(b), "l"(c));
    return d;
}

__device__ __forceinline__ float unpack_sum(unsigned long long a) {
    float lo = __uint_as_float((unsigned)(a & 0xffffffffu));
    float hi = __uint_as_float((unsigned)(a >> 32));
    return lo + hi;
}

__device__ __forceinline__ unsigned long long pack2(float a, float b) {
    return (unsigned long long)__float_as_uint(a)
         | ((unsigned long long)__float_as_uint(b) << 32);
}

// ---------------- fused QKV projection + Minkowski self-products ----------
// Monolithic register-tiled GEMM (x-tile LDS amortized across q,k,v — the
// R12 sel-split tripled crossbar traffic and regressed). 256 threads, 32-row
// tile, 112KB smem -> TWO blocks per SM (the 131KB/512-thread version pinned
// occupancy at 1 block/SM, exposing LDS latency + staging/sync idle phases;
// two resident blocks interleave staging with compute). Per-thread work shape
// unchanged: thread (cc, rg) computes 8 rows x 3 sels, 24 packed-FFMA2 accs.
__global__ __launch_bounds__(256, 2) void qkv_kernel(
    const float* __restrict__ x,
    const float* __restrict__ Wq, const float* __restrict__ bq,
    const float* __restrict__ Wk, const float* __restrict__ bk,
    const float* __restrict__ Wv, const float* __restrict__ bv)
{
    extern __shared__ __align__(16) char smem[];
    float4* wsm = (float4*)smem;                       // [32][192] float4
    float4* xs4 = (float4*)(smem + 98304);             // [32][32]  float4

    int tid = threadIdx.x;
    int tile = blockIdx.x;
    int row0 = tile * 32;

    // ---- stage W transposed: wsm[k4*192 + sel*64 + cc] = W_sel[cc][4k4..] ----
    {
        const float4* Wsrc0 = (const float4*)Wq;
        const float4* Wsrc1 = (const float4*)Wk;
        const float4* Wsrc2 = (const float4*)Wv;
#pragma unroll
        for (int i = tid; i < 2048; i += 256) {
            int ccw = i >> 5, k4 = i & 31;
            wsm[k4 * 192 +       ccw] = Wsrc0[ccw * 32 + k4];
            wsm[k4 * 192 +  64 + ccw] = Wsrc1[ccw * 32 + k4];
            wsm[k4 * 192 + 128 + ccw] = Wsrc2[ccw * 32 + k4];
        }
    }

    // ---- stage x tile [32][128], zero-padded past NN ----
    {
        const float4* xg4 = (const float4*)(x + (size_t)row0 * 128);
#pragma unroll
        for (int i = tid; i < 1024; i += 256) {
            int row = i >> 5;
            float4 vz = make_float4(0.f, 0.f, 0.f, 0.f);
            if (row0 + row < NN) vz = xg4[i];
            xs4[i] = vz;
        }
    }
    __syncthreads();

    int cc = tid & 63;
    int rg = tid >> 6;     // 0..3 -> rows rg*8 .. rg*8+7

    unsigned long long aq[8], ak[8], av[8];
#pragma unroll
    for (int r = 0; r < 8; r++) { aq[r] = 0ull; ak[r] = 0ull; av[r] = 0ull; }

    const ulonglong2* ws2 = (const ulonglong2*)smem;
    const ulonglong2* xs2 = (const ulonglong2*)xs4;
    int xbase = rg * 8 * 32;

#pragma unroll 4
    for (int k4 = 0; k4 < 32; k4++) {
        ulonglong2 wqv = ws2[k4 * 192 +       cc];
        ulonglong2 wkv = ws2[k4 * 192 +  64 + cc];
        ulonglong2 wvv = ws2[k4 * 192 + 128 + cc];
#pragma unroll
        for (int r = 0; r < 8; r++) {
            ulonglong2 xv = xs2[xbase + r * 32 + k4];
            aq[r] = ffma2(wqv.x, xv.x, aq[r]);
            aq[r] = ffma2(wqv.y, xv.y, aq[r]);
            ak[r] = ffma2(wkv.x, xv.x, ak[r]);
            ak[r] = ffma2(wkv.y, xv.y, ak[r]);
            av[r] = ffma2(wvv.x, xv.x, av[r]);
            av[r] = ffma2(wvv.y, xv.y, av[r]);
        }
    }

    float bqv = bq[cc], bkv = bk[cc], bvv = bv[cc];
    float rq[8], rk[8];
    int rbase = row0 + rg * 8;
#pragma unroll
    for (int r = 0; r < 8; r++) {
        float vq = unpack_sum(aq[r]) + bqv;
        float vk = unpack_sum(ak[r]) + bkv;
        float vv = unpack_sum(av[r]) + bvv;
        rq[r] = vq; rk[r] = vk;
        int row = rbase + r;
        if (row < NN) {
            g_q[row * 64 + cc] = vq;
            g_k[row * 64 + cc] = vk;
            g_v[row * 64 + cc] = vv;
        }
    }

    // Minkowski self-products: reduce res^2*sign over the 16 lanes of each
    // head (warp = 32 consecutive cc -> two heads per warp)
    {
        float sign = ((cc & 15) == 15) ? -1.f : 1.f;
        int h = cc >> 4;
#pragma unroll
        for (int r = 0; r < 8; r++) {
            float pq = rq[r] * rq[r] * sign;
            float pk = rk[r] * rk[r] * sign;
            pq += __shfl_xor_sync(0xffffffffu, pq, 1);
            pk += __shfl_xor_sync(0xffffffffu, pk, 1);
            pq += __shfl_xor_sync(0xffffffffu, pq, 2);
            pk += __shfl_xor_sync(0xffffffffu, pk, 2);
            pq += __shfl_xor_sync(0xffffffffu, pq, 4);
            pk += __shfl_xor_sync(0xffffffffu, pk, 4);
            pq += __shfl_xor_sync(0xffffffffu, pq, 8);
            pk += __shfl_xor_sync(0xffffffffu, pk, 8);
            int row = rbase + r;
            if ((cc & 15) == 0 && row < NN) {
                g_qq[row * 4 + h] = pq;
                g_kk[row * 4 + h] = pk;
            }
        }
    }
}

// ---------------- histogram + dtype detect (CSR-chain stream) ---------------
// 782 blocks x 512 threads; each block histograms its 1024 edges (g_cnt
// starts all-zero). Per-block edge_index dtype detection (int64 vs int32:
// int32 read as int64 packs two indices into one word -> out-of-range w.h.p.)
__global__ __launch_bounds__(512) void hist_kernel(const void* __restrict__ ei) {
    __shared__ int s_is64;
    int tid = threadIdx.x;
    int tile = blockIdx.x;

    if (tid < 32) {
        const long long* e64 = (const long long*)ei;
        int ok = 1;
        for (int t = tid; t < 1024; t += 32) {
            long long v = e64[t];
            if (v < 0 || v >= NN) ok = 0;
        }
        unsigned b = __ballot_sync(0xffffffffu, ok);
        if (tid == 0) {
            int f = (b == 0xffffffffu) ? 1 : 0;
            s_is64 = f;
            if (tile == 0) g_is64 = f;
        }
    }
    __syncthreads();

    int is64 = s_is64;
#pragma unroll
    for (int u = 0; u < 2; u++) {
        long long e = (long long)tile * 1024 + u * 512 + tid;
        if (e < EE) {
            int dst = is64 ? (int)((const long long*)ei)[EE + e]
                           : ((const int*)ei)[EE + e];
            atomicAdd(&g_cnt[dst], 1);
        }
    }
}

// range allocation: order-free replacement for a prefix scan. Each node gets
// a contiguous chunk [off, off+cnt) via one aggregated atomic (REDUX.SUM).
// Re-zeroes g_cnt after reading (restores the cross-call invariant).
__global__ void alloc_kernel() {
    int i = blockIdx.x * blockDim.x + threadIdx.x;
    if (i >= NN) return;
    int c = g_cnt[i];
    g_cnt[i] = 0;
    int off = atomicAdd(&g_total, c);
    g_rs[i] = off;
    g_cur[i] = off;
}

// scatter: 2 edges per thread, vectorized index loads. Resets g_total.
__global__ void scatter_kernel(const void* ei) {
    int is64 = g_is64;
    int t = blockIdx.x * blockDim.x + threadIdx.x;
    if (t == 0) g_total = 0;
    if (t >= EE / 2) return;
    int s0, s1, d0, d1;
    if (is64) {
        const long long* e = (const long long*)ei;
        longlong2 sv = ((const longlong2*)e)[t];
        longlong2 dv = ((const longlong2*)(e + EE))[t];
        s0 = (int)sv.x; s1 = (int)sv.y;
        d0 = (int)dv.x; d1 = (int)dv.y;
    } else {
        const int* e = (const int*)ei;
        int2 sv = ((const int2*)e)[t];
        int2 dv = ((const int2*)(e + EE))[t];
        s0 = sv.x; s1 = sv.y;
        d0 = dv.x; d1 = dv.y;
    }
    g_csr[atomicAdd(&g_cur[d0], 1)] = s0;
    g_csr[atomicAdd(&g_cur[d1], 1)] = s1;
}

// ---------------- gather attention: lane-per-(edge,head) ---------------------
// One warp per dst node, 8 edges per iteration. Dot role: lane l handles edge
// e=l>>2, head h'=l&3 -> full 16-dim Minkowski dot computed IN-LANE via 8
// FFMA2 against the k head held in registers (dim 15 pre-negated). Score math
// computed once per (edge,head) -- no warp-wide duplication, no dot shfls.
// Agg role: lane l owns flat dims {2l,2l+1} (head h=l>>3); per edge, src index
// and weight arrive via 2 shfl broadcasts.
// exp(-acosh(arg)) == 1/(arg + sqrt(arg^2-1))  -> no MUFU log/exp.
// Softmax denom cancels exactly into the L2 norm: att = S / (||S|| + EPS*s).
// NOTE: plain launch_bounds -- both reg-capping (R11) and SW pipelining (R9)
// regressed this kernel; 48 regs / occ 50% is its stable operating point.
__global__ __launch_bounds__(256) void attn_kernel() {
    int gtid = blockIdx.x * blockDim.x + threadIdx.x;
    int i = gtid >> 5;
    if (i >= NN) return;
    int lane = threadIdx.x & 31;
    int hp = lane & 3;      // dot-role head
    int er = lane >> 2;     // dot-role edge slot (0..7)
    int h  = lane >> 3;     // agg-role head

    // k head h' packed into 8 f32x2 registers, dim 15 negated (Minkowski)
    unsigned long long kd[8];
    {
        const float4* kp = (const float4*)(g_k + i * 64 + hp * 16);
        float4 k0 = kp[0], k1 = kp[1], k2 = kp[2], k3 = kp[3];
        k3.w = -k3.w;
        kd[0] = pack2(k0.x, k0.y); kd[1] = pack2(k0.z, k0.w);
        kd[2] = pack2(k1.x, k1.y); kd[3] = pack2(k1.z, k1.w);
        kd[4] = pack2(k2.x, k2.y); kd[5] = pack2(k2.z, k2.w);
        kd[6] = pack2(k3.x, k3.y); kd[7] = pack2(k3.z, k3.w);
    }
    float kkv = g_kk[i * 4 + hp];

    int js = g_rs[i];
    int je = g_cur[i];

    float s = 0.f, a0 = 0.f, a1 = 0.f;
    const float CLMP = (1.0f + 1e-6f) * (1.0f + 1e-6f);

    for (int j = js; j < je; j += 8) {
        int pos = j + er;
        int valid = pos < je;
        int src = valid ? g_csr[pos] : 0;

        // in-lane 16-dim Minkowski dot (two chains for ILP)
        const ulonglong2* qp = (const ulonglong2*)(g_q + src * 64 + hp * 16);
        ulonglong2 qa = qp[0], qb = qp[1], qc = qp[2], qd = qp[3];
        unsigned long long accA = 0ull, accB = 0ull;
        accA = ffma2(qa.x, kd[0], accA);
        accB = ffma2(qa.y, kd[1], accB);
        accA = ffma2(qb.x, kd[2], accA);
        accB = ffma2(qb.y, kd[3], accB);
        accA = ffma2(qc.x, kd[4], accA);
        accB = ffma2(qc.y, kd[5], accB);
        accA = ffma2(qd.x, kd[6], accA);
        accB = ffma2(qd.y, kd[7], accB);
        float d = unpack_sum(accA) + unpack_sum(accB);

        float qq = g_qq[src * 4 + hp];
        float r = __fdividef(d * d, fmaxf(fabsf(qq * kkv), 1e-9f)) + 1e-9f;
        r = fmaxf(r, CLMP);
        float p = __frcp_rn(sqrtf(r) + sqrtf(r - 1.0f));
        if (!valid) p = 0.f;

        // aggregation: dims {2*lane, 2*lane+1}, head h = lane>>3
#pragma unroll
        for (int e = 0; e < 8; e++) {
            int   sr = __shfl_sync(0xffffffffu, src, e * 4);
            float pw = __shfl_sync(0xffffffffu, p,   e * 4 + h);
            float2 vv = *(const float2*)(g_v + sr * 64 + 2 * lane);
            a0 = fmaf(pw, vv.x, a0);
            a1 = fmaf(pw, vv.y, a1);
            s += pw;
        }
    }

    float nsq = fmaf(a0, a0, a1 * a1);
    nsq += __shfl_xor_sync(0xffffffffu, nsq, 1);
    nsq += __shfl_xor_sync(0xffffffffu, nsq, 2);
    nsq += __shfl_xor_sync(0xffffffffu, nsq, 4);
    float norm = sqrtf(nsq);
    // agg = S/s, attended = agg/(||agg||+EPS) = S/(||S|| + EPS*s); 0 if no mass
    float scale = (norm > 0.f) ? __frcp_rn(norm + 1e-9f * s) : 0.f;
    float2 o;
    o.x = a0 * scale;
    o.y = a1 * scale;
    *(float2*)(g_att + i * 64 + 2 * lane) = o;
}

// ---------------- output projection: [N,64] x [64,64]^T + bias --------------
// 256-thread blocks = 4 independent 16-row tiles (64 columns each), FFMA2.
// Wo read is amortized over 16 rows per tile (per-node Wo reads were the
// R4/R5 regression).
__global__ __launch_bounds__(256) void out_kernel(
    const float* __restrict__ Wo, const float* __restrict__ bo,
    float* __restrict__ out)
{
    __shared__ __align__(16) float as[4][16 * 64];
    int grp = threadIdx.x >> 6;     // tile within block
    int tid = threadIdx.x & 63;     // column
    int tile = blockIdx.x * 4 + grp;
    if (tile >= 3125) return;       // 3125 tiles * 16 rows = 50000

    const float4* ag = (const float4*)(g_att + (size_t)tile * 16 * 64);
    float4* as4 = (float4*)as[grp];
    for (int i = tid; i < 256; i += 64) as4[i] = ag[i];
    __syncthreads();

    unsigned long long acc[16];
#pragma unroll
    for (int r = 0; r < 16; r++) acc[r] = 0ull;

    const ulonglong2* Wr = (const ulonglong2*)(Wo + tid * 64);
    const ulonglong2* as2 = (const ulonglong2*)as[grp];
#pragma unroll 4
    for (int k4 = 0; k4 < 16; k4++) {
        ulonglong2 w = Wr[k4];
#pragma unroll
        for (int r = 0; r < 16; r++) {
            ulonglong2 a = as2[r * 16 + k4];
            acc[r] = ffma2(w.x, a.x, acc[r]);
            acc[r] = ffma2(w.y, a.y, acc[r]);
        }
    }

    float b = bo[tid];
    int row0 = tile * 16;
#pragma unroll
    for (int r = 0; r < 16; r++) out[(row0 + r) * 64 + tid] = unpack_sum(acc[r]) + b;
}

// ---------------- launch: fork-join (CSR chain || QKV), join before attn -----
extern "C" void kernel_launch(void* const* d_in, const int* in_sizes, int n_in,
                              void* d_out, int out_size) {
    const float* x  = (const float*)d_in[0];
    const void*  ei = d_in[1];
    const float* Wq = (const float*)d_in[2];
    const float* bq = (const float*)d_in[3];
    const float* Wk = (const float*)d_in[4];
    const float* bk = (const float*)d_in[5];
    const float* Wv = (const float*)d_in[6];
    const float* bv = (const float*)d_in[7];
    const float* Wo = (const float*)d_in[8];
    const float* bo = (const float*)d_in[9];
    float* out = (float*)d_out;

    cudaFuncSetAttribute(qkv_kernel,
                         cudaFuncAttributeMaxDynamicSharedMemorySize, QKV_SMEM);

    cudaStream_t s2;
    cudaStreamCreateWithFlags(&s2, cudaStreamNonBlocking);
    cudaEvent_t eF, eJ;
    cudaEventCreateWithFlags(&eF, cudaEventDisableTiming);
    cudaEventCreateWithFlags(&eJ, cudaEventDisableTiming);

    // fork: CSR chain on s2 runs concurrently with qkv on the main stream
    cudaEventRecord(eF, 0);
    cudaStreamWaitEvent(s2, eF, 0);
    hist_kernel<<<CSR_BLOCKS, 512, 0, s2>>>(ei);
    alloc_kernel<<<(NN + 255) / 256, 256, 0, s2>>>();
    scatter_kernel<<<(EE / 2 + 255) / 256, 256, 0, s2>>>(ei);
    cudaEventRecord(eJ, s2);

    qkv_kernel<<<QKV_BLOCKS, 256, QKV_SMEM>>>(x, Wq, bq, Wk, bk, Wv, bv);

    // join: attn needs both qkv outputs and the CSR
    cudaStreamWaitEvent(0, eJ, 0);
    attn_kernel<<<(NN * 32) / 256, 256>>>();
    out_kernel<<<(3125 + 3) / 4, 256>>>(Wo, bo, out);

    cudaEventDestroy(eF);
    cudaEventDestroy(eJ);
    cudaStreamDestroy(s2);
}

// round 15
// speedup vs baseline: 1.1132x; 1.1132x over previous
#include <cuda_runtime.h>
#include <math.h>
#include <stdint.h>

#define NN 50000
#define EE 800000
#define INF_F 128
#define OUTF 64
#define HH 4
#define DD 16

#define CSR_BLOCKS 782            // ceil(800000/1024) edge slices
#define QKV_TILES  782            // ceil(50000/64)
#define QKV_GRID   148            // persistent: one block per SM
#define QKV_SMEM   (98304 + 2 * 32768)   // 96KB W + double-buffered 32KB x

// ---------------- device scratch (no allocations allowed) ----------------
// Invariants maintained ACROSS calls (restored within each call):
//   g_cnt[] == 0  (zero-init at load; alloc_kernel re-zeroes after reading)
//   g_total == 0  (zero-init at load; scatter_kernel resets)
__device__ float g_q[NN * OUTF];
__device__ float g_k[NN * OUTF];
__device__ float g_v[NN * OUTF];
__device__ float g_att[NN * OUTF];
__device__ float g_qq[NN * HH];
__device__ float g_kk[NN * HH];
__device__ int   g_cnt[NN];
__device__ int   g_rs[NN];
__device__ int   g_cur[NN];
__device__ int   g_csr[EE];
__device__ int   g_is64;
__device__ int   g_total;

// packed f32x2 FMA: d = a*b + c elementwise on packed pairs (Blackwell FFMA2)
__device__ __forceinline__ unsigned long long ffma2(
    unsigned long long a, unsigned long long b, unsigned long long c)
{
    unsigned long long d;
    asm("fma.rn.f32x2 %0, %1, %2, %3;" : "=l"(d) : "l"(a), "l"(b), "l"(c));
    return d;
}

__device__ __forceinline__ float unpack_sum(unsigned long long a) {
    float lo = __uint_as_float((unsigned)(a & 0xffffffffu));
    float hi = __uint_as_float((unsigned)(a >> 32));
    return lo + hi;
}

__device__ __forceinline__ unsigned long long pack2(float a, float b) {
    return (unsigned long long)__float_as_uint(a)
         | ((unsigned long long)__float_as_uint(b) << 32);
}

__device__ __forceinline__ uint32_t smem_u32(const void* p) {
    uint32_t a;
    asm("{ .reg .u64 t; cvta.to.shared.u64 t, %1; cvt.u32.u64 %0, t; }"
        : "=r"(a) : "l"(p));
    return a;
}

// cp.async 16B with zero-fill predicate (src_size=0 -> zeros)
__device__ __forceinline__ void cp_async16(uint32_t dst, const void* src, int pred) {
    int sz = pred ? 16 : 0;
    asm volatile("cp.async.cg.shared.global [%0], [%1], 16, %2;\n"
                 :: "r"(dst), "l"(src), "r"(sz));
}
__device__ __forceinline__ void cp_commit() {
    asm volatile("cp.async.commit_group;\n");
}
template <int N>
__device__ __forceinline__ void cp_wait() {
    asm volatile("cp.async.wait_group %0;\n" :: "n"(N));
}

// ---------------- persistent fused QKV projection + self-products ----------
// Grid = 148 (one block/SM), each block loops tiles bid, bid+148, ... over the
// 782 64-row tiles. W (3x64x128 fp32, 96KB) is staged in smem ONCE per SM
// (the per-wave re-staging + wave transitions cost ~12-15us in the non-
// persistent version). x tiles are double-buffered via cp.async so the next
// tile's loads overlap the current tile's FFMA2 stream. Per-thread work shape
// identical to the proven R13 kernel: thread (cc, rg) computes 8 rows x 3
// sels with 24 packed-FFMA2 accumulators; x-tile LDS broadcast-amortized
// across q,k,v (R12 lesson).
__global__ __launch_bounds__(512) void qkv_kernel(
    const float* __restrict__ x,
    const float* __restrict__ Wq, const float* __restrict__ bq,
    const float* __restrict__ Wk, const float* __restrict__ bk,
    const float* __restrict__ Wv, const float* __restrict__ bv)
{
    extern __shared__ __align__(16) char smem[];
    float4* wsm = (float4*)smem;                       // [32][192] float4

    int tid = threadIdx.x;
    int bid = blockIdx.x;

    // ---- stage W transposed ONCE: wsm[k4*192 + sel*64 + cc] ----
    {
        const float4* Wsrc0 = (const float4*)Wq;
        const float4* Wsrc1 = (const float4*)Wk;
        const float4* Wsrc2 = (const float4*)Wv;
#pragma unroll
        for (int i = tid; i < 2048; i += 512) {
            int ccw = i >> 5, k4 = i & 31;
            wsm[k4 * 192 +       ccw] = Wsrc0[ccw * 32 + k4];
            wsm[k4 * 192 +  64 + ccw] = Wsrc1[ccw * 32 + k4];
            wsm[k4 * 192 + 128 + ccw] = Wsrc2[ccw * 32 + k4];
        }
    }

    uint32_t xb[2];
    xb[0] = smem_u32(smem + 98304);
    xb[1] = smem_u32(smem + 98304 + 32768);

    int cc = tid & 63;
    int rg = tid >> 6;     // 0..7 -> rows rg*8 .. rg*8+7
    float bqv = bq[cc], bkv = bk[cc], bvv = bv[cc];

    // ---- prefetch x for first tile into buffer 0 ----
    {
        int row0 = bid * 64;
        const float4* xg4 = (const float4*)(x + (size_t)row0 * 128);
#pragma unroll
        for (int i = tid; i < 2048; i += 512) {
            int row = i >> 5;
            cp_async16(xb[0] + i * 16, xg4 + i, (row0 + row) < NN);
        }
        cp_commit();
    }

    int idx = 0;
    for (int tile = bid; tile < QKV_TILES; tile += QKV_GRID, idx++) {
        int cur = idx & 1;
        int ntile = tile + QKV_GRID;
        if (ntile < QKV_TILES) {
            int nrow0 = ntile * 64;
            const float4* xg4 = (const float4*)(x + (size_t)nrow0 * 128);
#pragma unroll
            for (int i = tid; i < 2048; i += 512) {
                int row = i >> 5;
                cp_async16(xb[1 - cur] + i * 16, xg4 + i, (nrow0 + row) < NN);
            }
            cp_commit();
            cp_wait<1>();     // current buffer's group has landed
        } else {
            cp_wait<0>();
        }
        __syncthreads();      // buffer cur ready for all threads

        int row0 = tile * 64;
        unsigned long long aq[8], ak[8], av[8];
#pragma unroll
        for (int r = 0; r < 8; r++) { aq[r] = 0ull; ak[r] = 0ull; av[r] = 0ull; }

        const ulonglong2* ws2 = (const ulonglong2*)smem;
        const ulonglong2* xs2 = (const ulonglong2*)(smem + 98304 + 32768 * cur);
        int xbase = rg * 8 * 32;

#pragma unroll 4
        for (int k4 = 0; k4 < 32; k4++) {
            ulonglong2 wqv = ws2[k4 * 192 +       cc];
            ulonglong2 wkv = ws2[k4 * 192 +  64 + cc];
            ulonglong2 wvv = ws2[k4 * 192 + 128 + cc];
#pragma unroll
            for (int r = 0; r < 8; r++) {
                ulonglong2 xv = xs2[xbase + r * 32 + k4];
                aq[r] = ffma2(wqv.x, xv.x, aq[r]);
                aq[r] = ffma2(wqv.y, xv.y, aq[r]);
                ak[r] = ffma2(wkv.x, xv.x, ak[r]);
                ak[r] = ffma2(wkv.y, xv.y, ak[r]);
                av[r] = ffma2(wvv.x, xv.x, av[r]);
                av[r] = ffma2(wvv.y, xv.y, av[r]);
            }
        }

        float rq[8], rk[8];
        int rbase = row0 + rg * 8;
#pragma unroll
        for (int r = 0; r < 8; r++) {
            float vq = unpack_sum(aq[r]) + bqv;
            float vk = unpack_sum(ak[r]) + bkv;
            float vv = unpack_sum(av[r]) + bvv;
            rq[r] = vq; rk[r] = vk;
            int row = rbase + r;
            if (row < NN) {
                g_q[row * 64 + cc] = vq;
                g_k[row * 64 + cc] = vk;
                g_v[row * 64 + cc] = vv;
            }
        }

        // Minkowski self-products: reduce res^2*sign over the 16 lanes of
        // each head (warp = 32 consecutive cc -> two heads per warp)
        {
            float sign = ((cc & 15) == 15) ? -1.f : 1.f;
            int h = cc >> 4;
#pragma unroll
            for (int r = 0; r < 8; r++) {
                float pq = rq[r] * rq[r] * sign;
                float pk = rk[r] * rk[r] * sign;
                pq += __shfl_xor_sync(0xffffffffu, pq, 1);
                pk += __shfl_xor_sync(0xffffffffu, pk, 1);
                pq += __shfl_xor_sync(0xffffffffu, pq, 2);
                pk += __shfl_xor_sync(0xffffffffu, pk, 2);
                pq += __shfl_xor_sync(0xffffffffu, pq, 4);
                pk += __shfl_xor_sync(0xffffffffu, pk, 4);
                pq += __shfl_xor_sync(0xffffffffu, pq, 8);
                pk += __shfl_xor_sync(0xffffffffu, pk, 8);
                int row = rbase + r;
                if ((cc & 15) == 0 && row < NN) {
                    g_qq[row * 4 + h] = pq;
                    g_kk[row * 4 + h] = pk;
                }
            }
        }
        __syncthreads();      // all reads of buffer cur done before next
                              // iteration's prefetch overwrites it
    }
}

// ---------------- histogram + dtype detect (CSR-chain stream) ---------------
// 782 blocks x 512 threads; each block histograms its 1024 edges (g_cnt
// starts all-zero). Per-block edge_index dtype detection (int64 vs int32:
// int32 read as int64 packs two indices into one word -> out-of-range w.h.p.)
__global__ __launch_bounds__(512) void hist_kernel(const void* __restrict__ ei) {
    __shared__ int s_is64;
    int tid = threadIdx.x;
    int tile = blockIdx.x;

    if (tid < 32) {
        const long long* e64 = (const long long*)ei;
        int ok = 1;
        for (int t = tid; t < 1024; t += 32) {
            long long v = e64[t];
            if (v < 0 || v >= NN) ok = 0;
        }
        unsigned b = __ballot_sync(0xffffffffu, ok);
        if (tid == 0) {
            int f = (b == 0xffffffffu) ? 1 : 0;
            s_is64 = f;
            if (tile == 0) g_is64 = f;
        }
    }
    __syncthreads();

    int is64 = s_is64;
#pragma unroll
    for (int u = 0; u < 2; u++) {
        long long e = (long long)tile * 1024 + u * 512 + tid;
        if (e < EE) {
            int dst = is64 ? (int)((const long long*)ei)[EE + e]
                           : ((const int*)ei)[EE + e];
            atomicAdd(&g_cnt[dst], 1);
        }
    }
}

// range allocation: order-free replacement for a prefix scan. Each node gets
// a contiguous chunk [off, off+cnt) via one aggregated atomic (REDUX.SUM).
// Re-zeroes g_cnt after reading (restores the cross-call invariant).
__global__ void alloc_kernel() {
    int i = blockIdx.x * blockDim.x + threadIdx.x;
    if (i >= NN) return;
    int c = g_cnt[i];
    g_cnt[i] = 0;
    int off = atomicAdd(&g_total, c);
    g_rs[i] = off;
    g_cur[i] = off;
}

// scatter: 2 edges per thread, vectorized index loads. Resets g_total.
__global__ void scatter_kernel(const void* ei) {
    int is64 = g_is64;
    int t = blockIdx.x * blockDim.x + threadIdx.x;
    if (t == 0) g_total = 0;
    if (t >= EE / 2) return;
    int s0, s1, d0, d1;
    if (is64) {
        const long long* e = (const long long*)ei;
        longlong2 sv = ((const longlong2*)e)[t];
        longlong2 dv = ((const longlong2*)(e + EE))[t];
        s0 = (int)sv.x; s1 = (int)sv.y;
        d0 = (int)dv.x; d1 = (int)dv.y;
    } else {
        const int* e = (const int*)ei;
        int2 sv = ((const int2*)e)[t];
        int2 dv = ((const int2*)(e + EE))[t];
        s0 = sv.x; s1 = sv.y;
        d0 = dv.x; d1 = dv.y;
    }
    g_csr[atomicAdd(&g_cur[d0], 1)] = s0;
    g_csr[atomicAdd(&g_cur[d1], 1)] = s1;
}

// ---------------- gather attention: lane-per-(edge,head) ---------------------
// One warp per dst node, 8 edges per iteration. Dot role: lane l handles edge
// e=l>>2, head h'=l&3 -> full 16-dim Minkowski dot computed IN-LANE via 8
// FFMA2 against the k head held in registers (dim 15 pre-negated). Score math
// computed once per (edge,head) -- no warp-wide duplication, no dot shfls.
// Agg role: lane l owns flat dims {2l,2l+1} (head h=l>>3); per edge, src index
// and weight arrive via 2 shfl broadcasts.
// exp(-acosh(arg)) == 1/(arg + sqrt(arg^2-1))  -> no MUFU log/exp.
// Softmax denom cancels exactly into the L2 norm: att = S / (||S|| + EPS*s).
// NOTE: plain launch_bounds -- both reg-capping (R11) and SW pipelining (R9)
// regressed this kernel; 48 regs / occ 50% is its stable operating point.
__global__ __launch_bounds__(256) void attn_kernel() {
    int gtid = blockIdx.x * blockDim.x + threadIdx.x;
    int i = gtid >> 5;
    if (i >= NN) return;
    int lane = threadIdx.x & 31;
    int hp = lane & 3;      // dot-role head
    int er = lane >> 2;     // dot-role edge slot (0..7)
    int h  = lane >> 3;     // agg-role head

    // k head h' packed into 8 f32x2 registers, dim 15 negated (Minkowski)
    unsigned long long kd[8];
    {
        const float4* kp = (const float4*)(g_k + i * 64 + hp * 16);
        float4 k0 = kp[0], k1 = kp[1], k2 = kp[2], k3 = kp[3];
        k3.w = -k3.w;
        kd[0] = pack2(k0.x, k0.y); kd[1] = pack2(k0.z, k0.w);
        kd[2] = pack2(k1.x, k1.y); kd[3] = pack2(k1.z, k1.w);
        kd[4] = pack2(k2.x, k2.y); kd[5] = pack2(k2.z, k2.w);
        kd[6] = pack2(k3.x, k3.y); kd[7] = pack2(k3.z, k3.w);
    }
    float kkv = g_kk[i * 4 + hp];

    int js = g_rs[i];
    int je = g_cur[i];

    float s = 0.f, a0 = 0.f, a1 = 0.f;
    const float CLMP = (1.0f + 1e-6f) * (1.0f + 1e-6f);

    for (int j = js; j < je; j += 8) {
        int pos = j + er;
        int valid = pos < je;
        int src = valid ? g_csr[pos] : 0;

        // in-lane 16-dim Minkowski dot (two chains for ILP)
        const ulonglong2* qp = (const ulonglong2*)(g_q + src * 64 + hp * 16);
        ulonglong2 qa = qp[0], qb = qp[1], qc = qp[2], qd = qp[3];
        unsigned long long accA = 0ull, accB = 0ull;
        accA = ffma2(qa.x, kd[0], accA);
        accB = ffma2(qa.y, kd[1], accB);
        accA = ffma2(qb.x, kd[2], accA);
        accB = ffma2(qb.y, kd[3], accB);
        accA = ffma2(qc.x, kd[4], accA);
        accB = ffma2(qc.y, kd[5], accB);
        accA = ffma2(qd.x, kd[6], accA);
        accB = ffma2(qd.y, kd[7], accB);
        float d = unpack_sum(accA) + unpack_sum(accB);

        float qq = g_qq[src * 4 + hp];
        float r = __fdividef(d * d, fmaxf(fabsf(qq * kkv), 1e-9f)) + 1e-9f;
        r = fmaxf(r, CLMP);
        float p = __frcp_rn(sqrtf(r) + sqrtf(r - 1.0f));
        if (!valid) p = 0.f;

        // aggregation: dims {2*lane, 2*lane+1}, head h = lane>>3
#pragma unroll
        for (int e = 0; e < 8; e++) {
            int   sr = __shfl_sync(0xffffffffu, src, e * 4);
            float pw = __shfl_sync(0xffffffffu, p,   e * 4 + h);
            float2 vv = *(const float2*)(g_v + sr * 64 + 2 * lane);
            a0 = fmaf(pw, vv.x, a0);
            a1 = fmaf(pw, vv.y, a1);
            s += pw;
        }
    }

    float nsq = fmaf(a0, a0, a1 * a1);
    nsq += __shfl_xor_sync(0xffffffffu, nsq, 1);
    nsq += __shfl_xor_sync(0xffffffffu, nsq, 2);
    nsq += __shfl_xor_sync(0xffffffffu, nsq, 4);
    float norm = sqrtf(nsq);
    // agg = S/s, attended = agg/(||agg||+EPS) = S/(||S|| + EPS*s); 0 if no mass
    float scale = (norm > 0.f) ? __frcp_rn(norm + 1e-9f * s) : 0.f;
    float2 o;
    o.x = a0 * scale;
    o.y = a1 * scale;
    *(float2*)(g_att + i * 64 + 2 * lane) = o;
}

// ---------------- output projection: [N,64] x [64,64]^T + bias --------------
// 256-thread blocks = 4 independent 16-row tiles (64 columns each), FFMA2.
// Wo read is amortized over 16 rows per tile (per-node Wo reads were the
// R4/R5 regression).
__global__ __launch_bounds__(256) void out_kernel(
    const float* __restrict__ Wo, const float* __restrict__ bo,
    float* __restrict__ out)
{
    __shared__ __align__(16) float as[4][16 * 64];
    int grp = threadIdx.x >> 6;     // tile within block
    int tid = threadIdx.x & 63;     // column
    int tile = blockIdx.x * 4 + grp;
    if (tile >= 3125) return;       // 3125 tiles * 16 rows = 50000

    const float4* ag = (const float4*)(g_att + (size_t)tile * 16 * 64);
    float4* as4 = (float4*)as[grp];
    for (int i = tid; i < 256; i += 64) as4[i] = ag[i];
    __syncthreads();

    unsigned long long acc[16];
#pragma unroll
    for (int r = 0; r < 16; r++) acc[r] = 0ull;

    const ulonglong2* Wr = (const ulonglong2*)(Wo + tid * 64);
    const ulonglong2* as2 = (const ulonglong2*)as[grp];
#pragma unroll 4
    for (int k4 = 0; k4 < 16; k4++) {
        ulonglong2 w = Wr[k4];
#pragma unroll
        for (int r = 0; r < 16; r++) {
            ulonglong2 a = as2[r * 16 + k4];
            acc[r] = ffma2(w.x, a.x, acc[r]);
            acc[r] = ffma2(w.y, a.y, acc[r]);
        }
    }

    float b = bo[tid];
    int row0 = tile * 16;
#pragma unroll
    for (int r = 0; r < 16; r++) out[(row0 + r) * 64 + tid] = unpack_sum(acc[r]) + b;
}

// ---------------- launch: fork-join (CSR chain || QKV), join before attn -----
extern "C" void kernel_launch(void* const* d_in, const int* in_sizes, int n_in,
                              void* d_out, int out_size) {
    const float* x  = (const float*)d_in[0];
    const void*  ei = d_in[1];
    const float* Wq = (const float*)d_in[2];
    const float* bq = (const float*)d_in[3];
    const float* Wk = (const float*)d_in[4];
    const float* bk = (const float*)d_in[5];
    const float* Wv = (const float*)d_in[6];
    const float* bv = (const float*)d_in[7];
    const float* Wo = (const float*)d_in[8];
    const float* bo = (const float*)d_in[9];
    float* out = (float*)d_out;

    cudaFuncSetAttribute(qkv_kernel,
                         cudaFuncAttributeMaxDynamicSharedMemorySize, QKV_SMEM);

    cudaStream_t s2;
    cudaStreamCreateWithFlags(&s2, cudaStreamNonBlocking);
    cudaEvent_t eF, eJ;
    cudaEventCreateWithFlags(&eF, cudaEventDisableTiming);
    cudaEventCreateWithFlags(&eJ, cudaEventDisableTiming);

    // fork: CSR chain on s2 runs concurrently with qkv on the main stream
    cudaEventRecord(eF, 0);
    cudaStreamWaitEvent(s2, eF, 0);
    hist_kernel<<<CSR_BLOCKS, 512, 0, s2>>>(ei);
    alloc_kernel<<<(NN + 255) / 256, 256, 0, s2>>>();
    scatter_kernel<<<(EE / 2 + 255) / 256, 256, 0, s2>>>(ei);
    cudaEventRecord(eJ, s2);

    qkv_kernel<<<QKV_GRID, 512, QKV_SMEM>>>(x, Wq, bq, Wk, bk, Wv, bv);

    // join: attn needs both qkv outputs and the CSR
    cudaStreamWaitEvent(0, eJ, 0);
    attn_kernel<<<(NN * 32) / 256, 256>>>();
    out_kernel<<<(3125 + 3) / 4, 256>>>(Wo, bo, out);

    cudaEventDestroy(eF);
    cudaEventDestroy(eJ);
    cudaStreamDestroy(s2);
}

// round 16
// speedup vs baseline: 1.2119x; 1.0886x over previous
#include <cuda_runtime.h>
#include <math.h>
#include <stdint.h>

#define NN 50000
#define EE 800000
#define INF_F 128
#define OUTF 64
#define HH 4
#define DD 16

#define CSR_BLOCKS 782            // ceil(800000/1024) edge slices
#define QKV_TILES  782            // ceil(50000/64)
#define QKV_GRID   148            // persistent: one block per SM
#define QKV_SMEM   (98304 + 2 * 32768)   // 96KB W + double-buffered 32KB x

// ---------------- device scratch (no allocations allowed) ----------------
// Invariants maintained ACROSS calls (restored within each call):
//   g_cnt[] == 0  (zero-init at load; alloc_kernel re-zeroes after reading)
//   g_total == 0  (zero-init at load; scatter_kernel resets)
__device__ float g_q[NN * OUTF];
__device__ float g_k[NN * OUTF];
__device__ float g_v[NN * OUTF];
__device__ float g_att[NN * OUTF];
__device__ float g_qq[NN * HH];
__device__ float g_kk[NN * HH];
__device__ int   g_cnt[NN];
__device__ int   g_rs[NN];
__device__ int   g_cur[NN];
__device__ int   g_csr[EE];
__device__ int   g_is64;
__device__ int   g_total;

// packed f32x2 FMA: d = a*b + c elementwise on packed pairs (Blackwell FFMA2)
__device__ __forceinline__ unsigned long long ffma2(
    unsigned long long a, unsigned long long b, unsigned long long c)
{
    unsigned long long d;
    asm("fma.rn.f32x2 %0, %1, %2, %3;" : "=l"(d) : "l"(a), "l"(b), "l"(c));
    return d;
}

__device__ __forceinline__ float unpack_sum(unsigned long long a) {
    float lo = __uint_as_float((unsigned)(a & 0xffffffffu));
    float hi = __uint_as_float((unsigned)(a >> 32));
    return lo + hi;
}

__device__ __forceinline__ unsigned long long pack2(float a, float b) {
    return (unsigned long long)__float_as_uint(a)
         | ((unsigned long long)__float_as_uint(b) << 32);
}

__device__ __forceinline__ uint32_t smem_u32(const void* p) {
    uint32_t a;
    asm("{ .reg .u64 t; cvta.to.shared.u64 t, %1; cvt.u32.u64 %0, t; }"
        : "=r"(a) : "l"(p));
    return a;
}

// cp.async 16B with zero-fill predicate (src_size=0 -> zeros)
__device__ __forceinline__ void cp_async16(uint32_t dst, const void* src, int pred) {
    int sz = pred ? 16 : 0;
    asm volatile("cp.async.cg.shared.global [%0], [%1], 16, %2;\n"
                 :: "r"(dst), "l"(src), "r"(sz));
}
__device__ __forceinline__ void cp_commit() {
    asm volatile("cp.async.commit_group;\n");
}
template <int N>
__device__ __forceinline__ void cp_wait() {
    asm volatile("cp.async.wait_group %0;\n" :: "n"(N));
}

// ---------------- persistent fused QKV projection + self-products ----------
// Grid = 148 (one block/SM), each block loops tiles bid, bid+148, ... over the
// 782 64-row tiles. W (3x64x128 fp32, 96KB) is staged in smem ONCE per SM.
// x tiles are double-buffered via cp.async so the next tile's loads overlap
// the current tile's FFMA2 stream. Per-thread work shape identical to the
// proven R13 kernel: thread (cc, rg) computes 8 rows x 3 sels with 24
// packed-FFMA2 accumulators; x-tile LDS broadcast-amortized across q,k,v.
__global__ __launch_bounds__(512) void qkv_kernel(
    const float* __restrict__ x,
    const float* __restrict__ Wq, const float* __restrict__ bq,
    const float* __restrict__ Wk, const float* __restrict__ bk,
    const float* __restrict__ Wv, const float* __restrict__ bv)
{
    extern __shared__ __align__(16) char smem[];
    float4* wsm = (float4*)smem;                       // [32][192] float4

    int tid = threadIdx.x;
    int bid = blockIdx.x;

    // ---- stage W transposed ONCE: wsm[k4*192 + sel*64 + cc] ----
    {
        const float4* Wsrc0 = (const float4*)Wq;
        const float4* Wsrc1 = (const float4*)Wk;
        const float4* Wsrc2 = (const float4*)Wv;
#pragma unroll
        for (int i = tid; i < 2048; i += 512) {
            int ccw = i >> 5, k4 = i & 31;
            wsm[k4 * 192 +       ccw] = Wsrc0[ccw * 32 + k4];
            wsm[k4 * 192 +  64 + ccw] = Wsrc1[ccw * 32 + k4];
            wsm[k4 * 192 + 128 + ccw] = Wsrc2[ccw * 32 + k4];
        }
    }

    uint32_t xb[2];
    xb[0] = smem_u32(smem + 98304);
    xb[1] = smem_u32(smem + 98304 + 32768);

    int cc = tid & 63;
    int rg = tid >> 6;     // 0..7 -> rows rg*8 .. rg*8+7
    float bqv = bq[cc], bkv = bk[cc], bvv = bv[cc];

    // ---- prefetch x for first tile into buffer 0 ----
    {
        int row0 = bid * 64;
        const float4* xg4 = (const float4*)(x + (size_t)row0 * 128);
#pragma unroll
        for (int i = tid; i < 2048; i += 512) {
            int row = i >> 5;
            cp_async16(xb[0] + i * 16, xg4 + i, (row0 + row) < NN);
        }
        cp_commit();
    }

    int idx = 0;
    for (int tile = bid; tile < QKV_TILES; tile += QKV_GRID, idx++) {
        int cur = idx & 1;
        int ntile = tile + QKV_GRID;
        if (ntile < QKV_TILES) {
            int nrow0 = ntile * 64;
            const float4* xg4 = (const float4*)(x + (size_t)nrow0 * 128);
#pragma unroll
            for (int i = tid; i < 2048; i += 512) {
                int row = i >> 5;
                cp_async16(xb[1 - cur] + i * 16, xg4 + i, (nrow0 + row) < NN);
            }
            cp_commit();
            cp_wait<1>();     // current buffer's group has landed
        } else {
            cp_wait<0>();
        }
        __syncthreads();      // buffer cur ready for all threads

        int row0 = tile * 64;
        unsigned long long aq[8], ak[8], av[8];
#pragma unroll
        for (int r = 0; r < 8; r++) { aq[r] = 0ull; ak[r] = 0ull; av[r] = 0ull; }

        const ulonglong2* ws2 = (const ulonglong2*)smem;
        const ulonglong2* xs2 = (const ulonglong2*)(smem + 98304 + 32768 * cur);
        int xbase = rg * 8 * 32;

#pragma unroll 4
        for (int k4 = 0; k4 < 32; k4++) {
            ulonglong2 wqv = ws2[k4 * 192 +       cc];
            ulonglong2 wkv = ws2[k4 * 192 +  64 + cc];
            ulonglong2 wvv = ws2[k4 * 192 + 128 + cc];
#pragma unroll
            for (int r = 0; r < 8; r++) {
                ulonglong2 xv = xs2[xbase + r * 32 + k4];
                aq[r] = ffma2(wqv.x, xv.x, aq[r]);
                aq[r] = ffma2(wqv.y, xv.y, aq[r]);
                ak[r] = ffma2(wkv.x, xv.x, ak[r]);
                ak[r] = ffma2(wkv.y, xv.y, ak[r]);
                av[r] = ffma2(wvv.x, xv.x, av[r]);
                av[r] = ffma2(wvv.y, xv.y, av[r]);
            }
        }

        float rq[8], rk[8];
        int rbase = row0 + rg * 8;
#pragma unroll
        for (int r = 0; r < 8; r++) {
            float vq = unpack_sum(aq[r]) + bqv;
            float vk = unpack_sum(ak[r]) + bkv;
            float vv = unpack_sum(av[r]) + bvv;
            rq[r] = vq; rk[r] = vk;
            int row = rbase + r;
            if (row < NN) {
                g_q[row * 64 + cc] = vq;
                g_k[row * 64 + cc] = vk;
                g_v[row * 64 + cc] = vv;
            }
        }

        // Minkowski self-products: reduce res^2*sign over the 16 lanes of
        // each head (warp = 32 consecutive cc -> two heads per warp)
        {
            float sign = ((cc & 15) == 15) ? -1.f : 1.f;
            int h = cc >> 4;
#pragma unroll
            for (int r = 0; r < 8; r++) {
                float pq = rq[r] * rq[r] * sign;
                float pk = rk[r] * rk[r] * sign;
                pq += __shfl_xor_sync(0xffffffffu, pq, 1);
                pk += __shfl_xor_sync(0xffffffffu, pk, 1);
                pq += __shfl_xor_sync(0xffffffffu, pq, 2);
                pk += __shfl_xor_sync(0xffffffffu, pk, 2);
                pq += __shfl_xor_sync(0xffffffffu, pq, 4);
                pk += __shfl_xor_sync(0xffffffffu, pk, 4);
                pq += __shfl_xor_sync(0xffffffffu, pq, 8);
                pk += __shfl_xor_sync(0xffffffffu, pk, 8);
                int row = rbase + r;
                if ((cc & 15) == 0 && row < NN) {
                    g_qq[row * 4 + h] = pq;
                    g_kk[row * 4 + h] = pk;
                }
            }
        }
        __syncthreads();      // all reads of buffer cur done before next
                              // iteration's prefetch overwrites it
    }
}

// ---------------- histogram + dtype detect (CSR-chain stream) ---------------
// 782 blocks x 512 threads; each block histograms its 1024 edges (g_cnt
// starts all-zero). Per-block edge_index dtype detection (int64 vs int32:
// int32 read as int64 packs two indices into one word -> out-of-range w.h.p.)
__global__ __launch_bounds__(512) void hist_kernel(const void* __restrict__ ei) {
    __shared__ int s_is64;
    int tid = threadIdx.x;
    int tile = blockIdx.x;

    if (tid < 32) {
        const long long* e64 = (const long long*)ei;
        int ok = 1;
        for (int t = tid; t < 1024; t += 32) {
            long long v = e64[t];
            if (v < 0 || v >= NN) ok = 0;
        }
        unsigned b = __ballot_sync(0xffffffffu, ok);
        if (tid == 0) {
            int f = (b == 0xffffffffu) ? 1 : 0;
            s_is64 = f;
            if (tile == 0) g_is64 = f;
        }
    }
    __syncthreads();

    int is64 = s_is64;
#pragma unroll
    for (int u = 0; u < 2; u++) {
        long long e = (long long)tile * 1024 + u * 512 + tid;
        if (e < EE) {
            int dst = is64 ? (int)((const long long*)ei)[EE + e]
                           : ((const int*)ei)[EE + e];
            atomicAdd(&g_cnt[dst], 1);
        }
    }
}

// range allocation: order-free replacement for a prefix scan. Each node gets
// a contiguous chunk [off, off+cnt) via one aggregated atomic (REDUX.SUM).
// Re-zeroes g_cnt after reading (restores the cross-call invariant).
__global__ void alloc_kernel() {
    int i = blockIdx.x * blockDim.x + threadIdx.x;
    if (i >= NN) return;
    int c = g_cnt[i];
    g_cnt[i] = 0;
    int off = atomicAdd(&g_total, c);
    g_rs[i] = off;
    g_cur[i] = off;
}

// scatter: 2 edges per thread, vectorized index loads. Resets g_total.
__global__ void scatter_kernel(const void* ei) {
    int is64 = g_is64;
    int t = blockIdx.x * blockDim.x + threadIdx.x;
    if (t == 0) g_total = 0;
    if (t >= EE / 2) return;
    int s0, s1, d0, d1;
    if (is64) {
        const long long* e = (const long long*)ei;
        longlong2 sv = ((const longlong2*)e)[t];
        longlong2 dv = ((const longlong2*)(e + EE))[t];
        s0 = (int)sv.x; s1 = (int)sv.y;
        d0 = (int)dv.x; d1 = (int)dv.y;
    } else {
        const int* e = (const int*)ei;
        int2 sv = ((const int2*)e)[t];
        int2 dv = ((const int2*)(e + EE))[t];
        s0 = sv.x; s1 = sv.y;
        d0 = dv.x; d1 = dv.y;
    }
    g_csr[atomicAdd(&g_cur[d0], 1)] = s0;
    g_csr[atomicAdd(&g_cur[d1], 1)] = s1;
}

// ---------------- gather attention: lane-per-(edge,head) ---------------------
// One warp per dst node, 8 edges per iteration. Dot role: lane l handles edge
// e=l>>2, head h'=l&3 -> full 16-dim Minkowski dot computed IN-LANE via 8
// FFMA2 against the k head held in registers (dim 15 pre-negated). Score math
// computed once per (edge,head) -- no warp-wide duplication, no dot shfls.
// Agg role: lane l owns flat dims {2l,2l+1} (head h=l>>3); per edge, src index
// and weight arrive via 2 shfl broadcasts.
// NEW (R16): the NEXT group's csr index is prefetched (clamped, in-bounds) at
// the top of the current group, breaking the serial index->gather dependency
// (two chained L2 trips) at each group head. Index-only: ~2 extra regs, unlike
// the R9 full-data pipeline (63 regs) that collapsed occupancy.
// exp(-acosh(arg)) == 1/(arg + sqrt(arg^2-1))  -> no MUFU log/exp.
// Softmax denom cancels exactly into the L2 norm: att = S / (||S|| + EPS*s).
// NOTE: plain launch_bounds -- reg-capping (R11) regressed this kernel.
__global__ __launch_bounds__(256) void attn_kernel() {
    int gtid = blockIdx.x * blockDim.x + threadIdx.x;
    int i = gtid >> 5;
    if (i >= NN) return;
    int lane = threadIdx.x & 31;
    int hp = lane & 3;      // dot-role head
    int er = lane >> 2;     // dot-role edge slot (0..7)
    int h  = lane >> 3;     // agg-role head

    // k head h' packed into 8 f32x2 registers, dim 15 negated (Minkowski)
    unsigned long long kd[8];
    {
        const float4* kp = (const float4*)(g_k + i * 64 + hp * 16);
        float4 k0 = kp[0], k1 = kp[1], k2 = kp[2], k3 = kp[3];
        k3.w = -k3.w;
        kd[0] = pack2(k0.x, k0.y); kd[1] = pack2(k0.z, k0.w);
        kd[2] = pack2(k1.x, k1.y); kd[3] = pack2(k1.z, k1.w);
        kd[4] = pack2(k2.x, k2.y); kd[5] = pack2(k2.z, k2.w);
        kd[6] = pack2(k3.x, k3.y); kd[7] = pack2(k3.z, k3.w);
    }
    float kkv = g_kk[i * 4 + hp];

    int js = g_rs[i];
    int je = g_cur[i];

    float s = 0.f, a0 = 0.f, a1 = 0.f;
    const float CLMP = (1.0f + 1e-6f) * (1.0f + 1e-6f);

    // index prologue: group 0's (clamped) csr index
    int srcNext = 0;
    if (je > js) {
        int p0 = js + er;
        srcNext = g_csr[min(p0, je - 1)];
    }

    for (int j = js; j < je; j += 8) {
        int src = srcNext;
        int valid = (j + er) < je;

        // prefetch next group's index (clamped -> always in-bounds; je-1 >= js
        // >= 0 because the loop was entered)
        int posN = j + 8 + er;
        srcNext = g_csr[min(posN, je - 1)];

        // in-lane 16-dim Minkowski dot (two chains for ILP)
        const ulonglong2* qp = (const ulonglong2*)(g_q + src * 64 + hp * 16);
        ulonglong2 qa = qp[0], qb = qp[1], qc = qp[2], qd = qp[3];
        unsigned long long accA = 0ull, accB = 0ull;
        accA = ffma2(qa.x, kd[0], accA);
        accB = ffma2(qa.y, kd[1], accB);
        accA = ffma2(qb.x, kd[2], accA);
        accB = ffma2(qb.y, kd[3], accB);
        accA = ffma2(qc.x, kd[4], accA);
        accB = ffma2(qc.y, kd[5], accB);
        accA = ffma2(qd.x, kd[6], accA);
        accB = ffma2(qd.y, kd[7], accB);
        float d = unpack_sum(accA) + unpack_sum(accB);

        float qq = g_qq[src * 4 + hp];
        float r = __fdividef(d * d, fmaxf(fabsf(qq * kkv), 1e-9f)) + 1e-9f;
        r = fmaxf(r, CLMP);
        float p = __frcp_rn(sqrtf(r) + sqrtf(r - 1.0f));
        if (!valid) p = 0.f;

        // aggregation: dims {2*lane, 2*lane+1}, head h = lane>>3
#pragma unroll
        for (int e = 0; e < 8; e++) {
            int   sr = __shfl_sync(0xffffffffu, src, e * 4);
            float pw = __shfl_sync(0xffffffffu, p,   e * 4 + h);
            float2 vv = *(const float2*)(g_v + sr * 64 + 2 * lane);
            a0 = fmaf(pw, vv.x, a0);
            a1 = fmaf(pw, vv.y, a1);
            s += pw;
        }
    }

    float nsq = fmaf(a0, a0, a1 * a1);
    nsq += __shfl_xor_sync(0xffffffffu, nsq, 1);
    nsq += __shfl_xor_sync(0xffffffffu, nsq, 2);
    nsq += __shfl_xor_sync(0xffffffffu, nsq, 4);
    float norm = sqrtf(nsq);
    // agg = S/s, attended = agg/(||agg||+EPS) = S/(||S|| + EPS*s); 0 if no mass
    float scale = (norm > 0.f) ? __frcp_rn(norm + 1e-9f * s) : 0.f;
    float2 o;
    o.x = a0 * scale;
    o.y = a1 * scale;
    *(float2*)(g_att + i * 64 + 2 * lane) = o;
}

// ---------------- output projection: [N,64] x [64,64]^T + bias --------------
// 256-thread blocks = 4 independent 16-row tiles (64 columns each), FFMA2.
// Wo read is amortized over 16 rows per tile (per-node Wo reads were the
// R4/R5 regression).
__global__ __launch_bounds__(256) void out_kernel(
    const float* __restrict__ Wo, const float* __restrict__ bo,
    float* __restrict__ out)
{
    __shared__ __align__(16) float as[4][16 * 64];
    int grp = threadIdx.x >> 6;     // tile within block
    int tid = threadIdx.x & 63;     // column
    int tile = blockIdx.x * 4 + grp;
    if (tile >= 3125) return;       // 3125 tiles * 16 rows = 50000

    const float4* ag = (const float4*)(g_att + (size_t)tile * 16 * 64);
    float4* as4 = (float4*)as[grp];
    for (int i = tid; i < 256; i += 64) as4[i] = ag[i];
    __syncthreads();

    unsigned long long acc[16];
#pragma unroll
    for (int r = 0; r < 16; r++) acc[r] = 0ull;

    const ulonglong2* Wr = (const ulonglong2*)(Wo + tid * 64);
    const ulonglong2* as2 = (const ulonglong2*)as[grp];
#pragma unroll 4
    for (int k4 = 0; k4 < 16; k4++) {
        ulonglong2 w = Wr[k4];
#pragma unroll
        for (int r = 0; r < 16; r++) {
            ulonglong2 a = as2[r * 16 + k4];
            acc[r] = ffma2(w.x, a.x, acc[r]);
            acc[r] = ffma2(w.y, a.y, acc[r]);
        }
    }

    float b = bo[tid];
    int row0 = tile * 16;
#pragma unroll
    for (int r = 0; r < 16; r++) out[(row0 + r) * 64 + tid] = unpack_sum(acc[r]) + b;
}

// ---------------- launch: fork-join (CSR chain || QKV), join before attn -----
extern "C" void kernel_launch(void* const* d_in, const int* in_sizes, int n_in,
                              void* d_out, int out_size) {
    const float* x  = (const float*)d_in[0];
    const void*  ei = d_in[1];
    const float* Wq = (const float*)d_in[2];
    const float* bq = (const float*)d_in[3];
    const float* Wk = (const float*)d_in[4];
    const float* bk = (const float*)d_in[5];
    const float* Wv = (const float*)d_in[6];
    const float* bv = (const float*)d_in[7];
    const float* Wo = (const float*)d_in[8];
    const float* bo = (const float*)d_in[9];
    float* out = (float*)d_out;

    cudaFuncSetAttribute(qkv_kernel,
                         cudaFuncAttributeMaxDynamicSharedMemorySize, QKV_SMEM);

    cudaStream_t s2;
    cudaStreamCreateWithFlags(&s2, cudaStreamNonBlocking);
    cudaEvent_t eF, eJ;
    cudaEventCreateWithFlags(&eF, cudaEventDisableTiming);
    cudaEventCreateWithFlags(&eJ, cudaEventDisableTiming);

    // fork: CSR chain on s2 runs concurrently with qkv on the main stream
    cudaEventRecord(eF, 0);
    cudaStreamWaitEvent(s2, eF, 0);
    hist_kernel<<<CSR_BLOCKS, 512, 0, s2>>>(ei);
    alloc_kernel<<<(NN + 255) / 256, 256, 0, s2>>>();
    scatter_kernel<<<(EE / 2 + 255) / 256, 256, 0, s2>>>(ei);
    cudaEventRecord(eJ, s2);

    qkv_kernel<<<QKV_GRID, 512, QKV_SMEM>>>(x, Wq, bq, Wk, bk, Wv, bv);

    // join: attn needs both qkv outputs and the CSR
    cudaStreamWaitEvent(0, eJ, 0);
    attn_kernel<<<(NN * 32) / 256, 256>>>();
    out_kernel<<<(3125 + 3) / 4, 256>>>(Wo, bo, out);

    cudaEventDestroy(eF);
    cudaEventDestroy(eJ);
    cudaStreamDestroy(s2);
}

// round 17
// speedup vs baseline: 1.2344x; 1.0186x over previous
#include <cuda_runtime.h>
#include <math.h>
#include <stdint.h>

#define NN 50000
#define EE 800000
#define INF_F 128
#define OUTF 64
#define HH 4
#define DD 16

#define CSR_BLOCKS 782            // ceil(800000/1024) edge slices
#define QKV_TILES  782            // ceil(50000/64)
#define QKV_GRID   148            // persistent: one block per SM
#define QKV_SMEM   (98304 + 2 * 32768)   // 96KB W + double-buffered 32KB x

// ---------------- device scratch (no allocations allowed) ----------------
// Invariants maintained ACROSS calls (restored within each call):
//   g_cnt[] == 0  (zero-init at load; alloc_kernel re-zeroes after reading)
//   g_total == 0  (zero-init at load; scatter_kernel resets)
__device__ float g_q[NN * OUTF];
__device__ float g_k[NN * OUTF];
__device__ float g_v[NN * OUTF];
__device__ float g_att[NN * OUTF];
__device__ float g_qq[NN * HH];
__device__ float g_kk[NN * HH];
__device__ int   g_cnt[NN];
__device__ int   g_rs[NN];
__device__ int   g_cur[NN];
__device__ int   g_csr[EE];
__device__ int   g_is64;
__device__ int   g_total;

// packed f32x2 FMA: d = a*b + c elementwise on packed pairs (Blackwell FFMA2)
__device__ __forceinline__ unsigned long long ffma2(
    unsigned long long a, unsigned long long b, unsigned long long c)
{
    unsigned long long d;
    asm("fma.rn.f32x2 %0, %1, %2, %3;" : "=l"(d) : "l"(a), "l"(b), "l"(c));
    return d;
}

__device__ __forceinline__ float unpack_sum(unsigned long long a) {
    float lo = __uint_as_float((unsigned)(a & 0xffffffffu));
    float hi = __uint_as_float((unsigned)(a >> 32));
    return lo + hi;
}

__device__ __forceinline__ unsigned long long pack2(float a, float b) {
    return (unsigned long long)__float_as_uint(a)
         | ((unsigned long long)__float_as_uint(b) << 32);
}

__device__ __forceinline__ uint32_t smem_u32(const void* p) {
    uint32_t a;
    asm("{ .reg .u64 t; cvta.to.shared.u64 t, %1; cvt.u32.u64 %0, t; }"
        : "=r"(a) : "l"(p));
    return a;
}

// cp.async 16B with zero-fill predicate (src_size=0 -> zeros)
__device__ __forceinline__ void cp_async16(uint32_t dst, const void* src, int pred) {
    int sz = pred ? 16 : 0;
    asm volatile("cp.async.cg.shared.global [%0], [%1], 16, %2;\n"
                 :: "r"(dst), "l"(src), "r"(sz));
}
__device__ __forceinline__ void cp_commit() {
    asm volatile("cp.async.commit_group;\n");
}
template <int N>
__device__ __forceinline__ void cp_wait() {
    asm volatile("cp.async.wait_group %0;\n" :: "n"(N));
}

// ---------------- persistent fused QKV projection + self-products ----------
// Grid = 148 (one block/SM), each block loops tiles bid, bid+148, ... over the
// 782 64-row tiles. W (3x64x128 fp32, 96KB) is staged in smem ONCE per SM.
// x tiles are double-buffered via cp.async so the next tile's loads overlap
// the current tile's FFMA2 stream. Per-thread work shape identical to the
// proven R13 kernel: thread (cc, rg) computes 8 rows x 3 sels with 24
// packed-FFMA2 accumulators; x-tile LDS broadcast-amortized across q,k,v.
// k4 loop at unroll 8 (R17): wider static window for hoisting the 11 LDS per
// step ahead of dependent FFMA2s -- at 16 warps/SM static scheduling is the
// only latency hiding available.
__global__ __launch_bounds__(512) void qkv_kernel(
    const float* __restrict__ x,
    const float* __restrict__ Wq, const float* __restrict__ bq,
    const float* __restrict__ Wk, const float* __restrict__ bk,
    const float* __restrict__ Wv, const float* __restrict__ bv)
{
    extern __shared__ __align__(16) char smem[];
    float4* wsm = (float4*)smem;                       // [32][192] float4

    int tid = threadIdx.x;
    int bid = blockIdx.x;

    // ---- stage W transposed ONCE: wsm[k4*192 + sel*64 + cc] ----
    {
        const float4* Wsrc0 = (const float4*)Wq;
        const float4* Wsrc1 = (const float4*)Wk;
        const float4* Wsrc2 = (const float4*)Wv;
#pragma unroll
        for (int i = tid; i < 2048; i += 512) {
            int ccw = i >> 5, k4 = i & 31;
            wsm[k4 * 192 +       ccw] = Wsrc0[ccw * 32 + k4];
            wsm[k4 * 192 +  64 + ccw] = Wsrc1[ccw * 32 + k4];
            wsm[k4 * 192 + 128 + ccw] = Wsrc2[ccw * 32 + k4];
        }
    }

    uint32_t xb[2];
    xb[0] = smem_u32(smem + 98304);
    xb[1] = smem_u32(smem + 98304 + 32768);

    int cc = tid & 63;
    int rg = tid >> 6;     // 0..7 -> rows rg*8 .. rg*8+7
    float bqv = bq[cc], bkv = bk[cc], bvv = bv[cc];

    // ---- prefetch x for first tile into buffer 0 ----
    {
        int row0 = bid * 64;
        const float4* xg4 = (const float4*)(x + (size_t)row0 * 128);
#pragma unroll
        for (int i = tid; i < 2048; i += 512) {
            int row = i >> 5;
            cp_async16(xb[0] + i * 16, xg4 + i, (row0 + row) < NN);
        }
        cp_commit();
    }

    int idx = 0;
    for (int tile = bid; tile < QKV_TILES; tile += QKV_GRID, idx++) {
        int cur = idx & 1;
        int ntile = tile + QKV_GRID;
        if (ntile < QKV_TILES) {
            int nrow0 = ntile * 64;
            const float4* xg4 = (const float4*)(x + (size_t)nrow0 * 128);
#pragma unroll
            for (int i = tid; i < 2048; i += 512) {
                int row = i >> 5;
                cp_async16(xb[1 - cur] + i * 16, xg4 + i, (nrow0 + row) < NN);
            }
            cp_commit();
            cp_wait<1>();     // current buffer's group has landed
        } else {
            cp_wait<0>();
        }
        __syncthreads();      // buffer cur ready for all threads

        int row0 = tile * 64;
        unsigned long long aq[8], ak[8], av[8];
#pragma unroll
        for (int r = 0; r < 8; r++) { aq[r] = 0ull; ak[r] = 0ull; av[r] = 0ull; }

        const ulonglong2* ws2 = (const ulonglong2*)smem;
        const ulonglong2* xs2 = (const ulonglong2*)(smem + 98304 + 32768 * cur);
        int xbase = rg * 8 * 32;

#pragma unroll 8
        for (int k4 = 0; k4 < 32; k4++) {
            ulonglong2 wqv = ws2[k4 * 192 +       cc];
            ulonglong2 wkv = ws2[k4 * 192 +  64 + cc];
            ulonglong2 wvv = ws2[k4 * 192 + 128 + cc];
#pragma unroll
            for (int r = 0; r < 8; r++) {
                ulonglong2 xv = xs2[xbase + r * 32 + k4];
                aq[r] = ffma2(wqv.x, xv.x, aq[r]);
                aq[r] = ffma2(wqv.y, xv.y, aq[r]);
                ak[r] = ffma2(wkv.x, xv.x, ak[r]);
                ak[r] = ffma2(wkv.y, xv.y, ak[r]);
                av[r] = ffma2(wvv.x, xv.x, av[r]);
                av[r] = ffma2(wvv.y, xv.y, av[r]);
            }
        }

        float rq[8], rk[8];
        int rbase = row0 + rg * 8;
#pragma unroll
        for (int r = 0; r < 8; r++) {
            float vq = unpack_sum(aq[r]) + bqv;
            float vk = unpack_sum(ak[r]) + bkv;
            float vv = unpack_sum(av[r]) + bvv;
            rq[r] = vq; rk[r] = vk;
            int row = rbase + r;
            if (row < NN) {
                g_q[row * 64 + cc] = vq;
                g_k[row * 64 + cc] = vk;
                g_v[row * 64 + cc] = vv;
            }
        }

        // Minkowski self-products: reduce res^2*sign over the 16 lanes of
        // each head (warp = 32 consecutive cc -> two heads per warp)
        {
            float sign = ((cc & 15) == 15) ? -1.f : 1.f;
            int h = cc >> 4;
#pragma unroll
            for (int r = 0; r < 8; r++) {
                float pq = rq[r] * rq[r] * sign;
                float pk = rk[r] * rk[r] * sign;
                pq += __shfl_xor_sync(0xffffffffu, pq, 1);
                pk += __shfl_xor_sync(0xffffffffu, pk, 1);
                pq += __shfl_xor_sync(0xffffffffu, pq, 2);
                pk += __shfl_xor_sync(0xffffffffu, pk, 2);
                pq += __shfl_xor_sync(0xffffffffu, pq, 4);
                pk += __shfl_xor_sync(0xffffffffu, pk, 4);
                pq += __shfl_xor_sync(0xffffffffu, pq, 8);
                pk += __shfl_xor_sync(0xffffffffu, pk, 8);
                int row = rbase + r;
                if ((cc & 15) == 0 && row < NN) {
                    g_qq[row * 4 + h] = pq;
                    g_kk[row * 4 + h] = pk;
                }
            }
        }
        __syncthreads();      // all reads of buffer cur done before next
                              // iteration's prefetch overwrites it
    }
}

// ---------------- histogram + dtype detect (CSR-chain stream) ---------------
// 782 blocks x 512 threads; each block histograms its 1024 edges (g_cnt
// starts all-zero). Per-block edge_index dtype detection (int64 vs int32:
// int32 read as int64 packs two indices into one word -> out-of-range w.h.p.)
__global__ __launch_bounds__(512) void hist_kernel(const void* __restrict__ ei) {
    __shared__ int s_is64;
    int tid = threadIdx.x;
    int tile = blockIdx.x;

    if (tid < 32) {
        const long long* e64 = (const long long*)ei;
        int ok = 1;
        for (int t = tid; t < 1024; t += 32) {
            long long v = e64[t];
            if (v < 0 || v >= NN) ok = 0;
        }
        unsigned b = __ballot_sync(0xffffffffu, ok);
        if (tid == 0) {
            int f = (b == 0xffffffffu) ? 1 : 0;
            s_is64 = f;
            if (tile == 0) g_is64 = f;
        }
    }
    __syncthreads();

    int is64 = s_is64;
#pragma unroll
    for (int u = 0; u < 2; u++) {
        long long e = (long long)tile * 1024 + u * 512 + tid;
        if (e < EE) {
            int dst = is64 ? (int)((const long long*)ei)[EE + e]
                           : ((const int*)ei)[EE + e];
            atomicAdd(&g_cnt[dst], 1);
        }
    }
}

// range allocation: order-free replacement for a prefix scan. Each node gets
// a contiguous chunk [off, off+cnt) via one aggregated atomic (REDUX.SUM).
// Re-zeroes g_cnt after reading (restores the cross-call invariant).
__global__ void alloc_kernel() {
    int i = blockIdx.x * blockDim.x + threadIdx.x;
    if (i >= NN) return;
    int c = g_cnt[i];
    g_cnt[i] = 0;
    int off = atomicAdd(&g_total, c);
    g_rs[i] = off;
    g_cur[i] = off;
}

// scatter: 2 edges per thread, vectorized index loads. Resets g_total.
__global__ void scatter_kernel(const void* ei) {
    int is64 = g_is64;
    int t = blockIdx.x * blockDim.x + threadIdx.x;
    if (t == 0) g_total = 0;
    if (t >= EE / 2) return;
    int s0, s1, d0, d1;
    if (is64) {
        const long long* e = (const long long*)ei;
        longlong2 sv = ((const longlong2*)e)[t];
        longlong2 dv = ((const longlong2*)(e + EE))[t];
        s0 = (int)sv.x; s1 = (int)sv.y;
        d0 = (int)dv.x; d1 = (int)dv.y;
    } else {
        const int* e = (const int*)ei;
        int2 sv = ((const int2*)e)[t];
        int2 dv = ((const int2*)(e + EE))[t];
        s0 = sv.x; s1 = sv.y;
        d0 = dv.x; d1 = dv.y;
    }
    g_csr[atomicAdd(&g_cur[d0], 1)] = s0;
    g_csr[atomicAdd(&g_cur[d1], 1)] = s1;
}

// ---------------- gather attention: lane-per-(edge,head) ---------------------
// One warp per dst node, 8 edges per iteration. Dot role: lane l handles edge
// e=l>>2, head h'=l&3 -> full 16-dim Minkowski dot computed IN-LANE via 8
// FFMA2 against the k head held in registers (dim 15 pre-negated). Score math
// computed once per (edge,head) -- no warp-wide duplication, no dot shfls.
// Agg role: lane l owns flat dims {2l,2l+1} (head h=l>>3); per edge, src index
// and weight arrive via 2 shfl broadcasts.
// Prefetch chain (R16/R17): next group's csr index AND its qq scalar are
// loaded ahead (clamped, in-bounds), breaking the serial index->qq->score
// dependency at each group head. ~3 extra regs total -- unlike the R9
// full-data pipeline (63 regs) that collapsed occupancy.
// exp(-acosh(arg)) == 1/(arg + sqrt(arg^2-1))  -> no MUFU log/exp.
// Softmax denom cancels exactly into the L2 norm: att = S / (||S|| + EPS*s).
// NOTE: plain launch_bounds -- reg-capping (R11) regressed this kernel.
__global__ __launch_bounds__(256) void attn_kernel() {
    int gtid = blockIdx.x * blockDim.x + threadIdx.x;
    int i = gtid >> 5;
    if (i >= NN) return;
    int lane = threadIdx.x & 31;
    int hp = lane & 3;      // dot-role head
    int er = lane >> 2;     // dot-role edge slot (0..7)
    int h  = lane >> 3;     // agg-role head

    // k head h' packed into 8 f32x2 registers, dim 15 negated (Minkowski)
    unsigned long long kd[8];
    {
        const float4* kp = (const float4*)(g_k + i * 64 + hp * 16);
        float4 k0 = kp[0], k1 = kp[1], k2 = kp[2], k3 = kp[3];
        k3.w = -k3.w;
        kd[0] = pack2(k0.x, k0.y); kd[1] = pack2(k0.z, k0.w);
        kd[2] = pack2(k1.x, k1.y); kd[3] = pack2(k1.z, k1.w);
        kd[4] = pack2(k2.x, k2.y); kd[5] = pack2(k2.z, k2.w);
        kd[6] = pack2(k3.x, k3.y); kd[7] = pack2(k3.z, k3.w);
    }
    float kkv = g_kk[i * 4 + hp];

    int js = g_rs[i];
    int je = g_cur[i];

    float s = 0.f, a0 = 0.f, a1 = 0.f;
    const float CLMP = (1.0f + 1e-6f) * (1.0f + 1e-6f);

    // prologue: group 0's (clamped) csr index + qq
    int srcNext = 0;
    float qqNext = 0.f;
    if (je > js) {
        int p0 = js + er;
        srcNext = g_csr[min(p0, je - 1)];
        qqNext = g_qq[srcNext * 4 + hp];
    }

    for (int j = js; j < je; j += 8) {
        int src = srcNext;
        float qq = qqNext;
        int valid = (j + er) < je;

        // prefetch next group's index + qq (clamped -> always in-bounds)
        int posN = j + 8 + er;
        srcNext = g_csr[min(posN, je - 1)];
        qqNext = g_qq[srcNext * 4 + hp];

        // in-lane 16-dim Minkowski dot (two chains for ILP)
        const ulonglong2* qp = (const ulonglong2*)(g_q + src * 64 + hp * 16);
        ulonglong2 qa = qp[0], qb = qp[1], qc = qp[2], qd = qp[3];
        unsigned long long accA = 0ull, accB = 0ull;
        accA = ffma2(qa.x, kd[0], accA);
        accB = ffma2(qa.y, kd[1], accB);
        accA = ffma2(qb.x, kd[2], accA);
        accB = ffma2(qb.y, kd[3], accB);
        accA = ffma2(qc.x, kd[4], accA);
        accB = ffma2(qc.y, kd[5], accB);
        accA = ffma2(qd.x, kd[6], accA);
        accB = ffma2(qd.y, kd[7], accB);
        float d = unpack_sum(accA) + unpack_sum(accB);

        float r = __fdividef(d * d, fmaxf(fabsf(qq * kkv), 1e-9f)) + 1e-9f;
        r = fmaxf(r, CLMP);
        float p = __frcp_rn(sqrtf(r) + sqrtf(r - 1.0f));
        if (!valid) p = 0.f;

        // aggregation: dims {2*lane, 2*lane+1}, head h = lane>>3
#pragma unroll
        for (int e = 0; e < 8; e++) {
            int   sr = __shfl_sync(0xffffffffu, src, e * 4);
            float pw = __shfl_sync(0xffffffffu, p,   e * 4 + h);
            float2 vv = *(const float2*)(g_v + sr * 64 + 2 * lane);
            a0 = fmaf(pw, vv.x, a0);
            a1 = fmaf(pw, vv.y, a1);
            s += pw;
        }
    }

    float nsq = fmaf(a0, a0, a1 * a1);
    nsq += __shfl_xor_sync(0xffffffffu, nsq, 1);
    nsq += __shfl_xor_sync(0xffffffffu, nsq, 2);
    nsq += __shfl_xor_sync(0xffffffffu, nsq, 4);
    float norm = sqrtf(nsq);
    // agg = S/s, attended = agg/(||agg||+EPS) = S/(||S|| + EPS*s); 0 if no mass
    float scale = (norm > 0.f) ? __frcp_rn(norm + 1e-9f * s) : 0.f;
    float2 o;
    o.x = a0 * scale;
    o.y = a1 * scale;
    *(float2*)(g_att + i * 64 + 2 * lane) = o;
}

// ---------------- output projection: [N,64] x [64,64]^T + bias --------------
// 256-thread blocks = 4 independent 16-row tiles (64 columns each), FFMA2.
// Wo read is amortized over 16 rows per tile (per-node Wo reads were the
// R4/R5 regression).
__global__ __launch_bounds__(256) void out_kernel(
    const float* __restrict__ Wo, const float* __restrict__ bo,
    float* __restrict__ out)
{
    __shared__ __align__(16) float as[4][16 * 64];
    int grp = threadIdx.x >> 6;     // tile within block
    int tid = threadIdx.x & 63;     // column
    int tile = blockIdx.x * 4 + grp;
    if (tile >= 3125) return;       // 3125 tiles * 16 rows = 50000

    const float4* ag = (const float4*)(g_att + (size_t)tile * 16 * 64);
    float4* as4 = (float4*)as[grp];
    for (int i = tid; i < 256; i += 64) as4[i] = ag[i];
    __syncthreads();

    unsigned long long acc[16];
#pragma unroll
    for (int r = 0; r < 16; r++) acc[r] = 0ull;

    const ulonglong2* Wr = (const ulonglong2*)(Wo + tid * 64);
    const ulonglong2* as2 = (const ulonglong2*)as[grp];
#pragma unroll 4
    for (int k4 = 0; k4 < 16; k4++) {
        ulonglong2 w = Wr[k4];
#pragma unroll
        for (int r = 0; r < 16; r++) {
            ulonglong2 a = as2[r * 16 + k4];
            acc[r] = ffma2(w.x, a.x, acc[r]);
            acc[r] = ffma2(w.y, a.y, acc[r]);
        }
    }

    float b = bo[tid];
    int row0 = tile * 16;
#pragma unroll
    for (int r = 0; r < 16; r++) out[(row0 + r) * 64 + tid] = unpack_sum(acc[r]) + b;
}

// ---------------- launch: fork-join (CSR chain || QKV), join before attn -----
extern "C" void kernel_launch(void* const* d_in, const int* in_sizes, int n_in,
                              void* d_out, int out_size) {
    const float* x  = (const float*)d_in[0];
    const void*  ei = d_in[1];
    const float* Wq = (const float*)d_in[2];
    const float* bq = (const float*)d_in[3];
    const float* Wk = (const float*)d_in[4];
    const float* bk = (const float*)d_in[5];
    const float* Wv = (const float*)d_in[6];
    const float* bv = (const float*)d_in[7];
    const float* Wo = (const float*)d_in[8];
    const float* bo = (const float*)d_in[9];
    float* out = (float*)d_out;

    cudaFuncSetAttribute(qkv_kernel,
                         cudaFuncAttributeMaxDynamicSharedMemorySize, QKV_SMEM);

    cudaStream_t s2;
    cudaStreamCreateWithFlags(&s2, cudaStreamNonBlocking);
    cudaEvent_t eF, eJ;
    cudaEventCreateWithFlags(&eF, cudaEventDisableTiming);
    cudaEventCreateWithFlags(&eJ, cudaEventDisableTiming);

    // fork: CSR chain on s2 runs concurrently with qkv on the main stream
    cudaEventRecord(eF, 0);
    cudaStreamWaitEvent(s2, eF, 0);
    hist_kernel<<<CSR_BLOCKS, 512, 0, s2>>>(ei);
    alloc_kernel<<<(NN + 255) / 256, 256, 0, s2>>>();
    scatter_kernel<<<(EE / 2 + 255) / 256, 256, 0, s2>>>(ei);
    cudaEventRecord(eJ, s2);

    qkv_kernel<<<QKV_GRID, 512, QKV_SMEM>>>(x, Wq, bq, Wk, bk, Wv, bv);

    // join: attn needs both qkv outputs and the CSR
    cudaStreamWaitEvent(0, eJ, 0);
    attn_kernel<<<(NN * 32) / 256, 256>>>();
    out_kernel<<<(3125 + 3) / 4, 256>>>(Wo, bo, out);

    cudaEventDestroy(eF);
    cudaEventDestroy(eJ);
    cudaStreamDestroy(s2);
}